// round 1
// baseline (speedup 1.0000x reference)
#include <cuda_runtime.h>

#define N_NODES 100000
#define N_EDGES 3200000
#define SLOTS   128

// ---------------- static scratch (no allocations allowed) ----------------
__device__ int    g_cnt  [N_NODES];
__device__ int    g_slots[N_NODES * SLOTS];   // CSR-by-dst: src indices
__device__ float  g_dinv [N_NODES];
__device__ float  g_xd   [N_NODES];           // dinv[n] * x[n]
__device__ float  g_s1   [N_NODES];           // scalar layer-1 aggregate
__device__ float  g_csum [N_NODES];           // sum over out-edges of dinv[dst]
__device__ float  g_cw   [N_NODES];           // dinv[n]*(csum[n]+dinv[n])
__device__ float  g_h2g  [N_NODES * 32];      // dinv[n] * (a1(n) @ W2)
__device__ double g_acc  [10];

// ---------------- kernel Z: zero the accumulators ----------------
__global__ void k_zero() {
    int i = blockIdx.x * blockDim.x + threadIdx.x;
    if (i < N_NODES) { g_cnt[i] = 0; g_csum[i] = 0.f; }
    if (i < 10) g_acc[i] = 0.0;
}

// ---------------- kernel B: histogram + slot scatter (CSR build) ----------------
__global__ void k_scatter(const int* __restrict__ src, const int* __restrict__ dst) {
    int e = blockIdx.x * blockDim.x + threadIdx.x;
    if (e >= N_EDGES) return;
    int d = dst[e];
    int s = src[e];
    int pos = atomicAdd(&g_cnt[d], 1);
    if (pos < SLOTS) g_slots[d * SLOTS + pos] = s;
}

// ---------------- kernel C: dinv + xd ----------------
__global__ void k_node_init(const float* __restrict__ x) {
    int n = blockIdx.x * blockDim.x + threadIdx.x;
    if (n >= N_NODES) return;
    float deg = (float)(g_cnt[n] + 1);        // +1 self loop
    float di = rsqrtf(deg);
    g_dinv[n] = di;
    g_xd[n]   = di * x[n];
}

// ---------------- kernel E0: warp-per-node scalar gather (s1) + csum atomics ----
__global__ void k_s1_csum() {
    int t = blockIdx.x * blockDim.x + threadIdx.x;
    int n = t >> 5;
    int lane = t & 31;
    if (n >= N_NODES) return;
    int cnt = g_cnt[n]; if (cnt > SLOTS) cnt = SLOTS;
    float du = g_dinv[n];
    const int* __restrict__ row = &g_slots[n * SLOTS];
    float acc = 0.f;
    for (int e = lane; e < cnt; e += 32) {
        int s = row[e];
        acc += g_xd[s];
        atomicAdd(&g_csum[s], du);            // covers each original edge once
    }
    #pragma unroll
    for (int o = 16; o; o >>= 1) acc += __shfl_down_sync(0xffffffffu, acc, o);
    if (lane == 0) g_s1[n] = du * (acc + g_xd[n]);   // + self-loop term
}

// ---------------- kernel E1: per-node MLP  h2g = dinv * (lrelu(s1*W1+b1) @ W2) ---
__global__ void k_mlp(const float* __restrict__ W1, const float* __restrict__ b1,
                      const float* __restrict__ W2) {
    __shared__ float sW1[64], sb1[64];
    __shared__ float sW2[64 * 32];
    int t = threadIdx.x;
    for (int i = t; i < 64; i += blockDim.x) { sW1[i] = W1[i]; sb1[i] = b1[i]; }
    for (int i = t; i < 64 * 32; i += blockDim.x) sW2[i] = W2[i];
    __syncthreads();

    int n = blockIdx.x * blockDim.x + t;
    if (n >= N_NODES) return;
    float s1 = g_s1[n];
    float di = g_dinv[n];

    float4 h[8];
    #pragma unroll
    for (int j = 0; j < 8; j++) h[j] = make_float4(0.f, 0.f, 0.f, 0.f);

    #pragma unroll 4
    for (int c = 0; c < 64; c++) {
        float a = fmaf(s1, sW1[c], sb1[c]);
        a = a > 0.f ? a : 0.1f * a;           // leaky_relu(0.1)
        const float4* w2r = (const float4*)&sW2[c * 32];
        #pragma unroll
        for (int j = 0; j < 8; j++) {
            float4 w = w2r[j];
            h[j].x = fmaf(a, w.x, h[j].x);
            h[j].y = fmaf(a, w.y, h[j].y);
            h[j].z = fmaf(a, w.z, h[j].z);
            h[j].w = fmaf(a, w.w, h[j].w);
        }
    }
    float4* out = (float4*)&g_h2g[n * 32];
    #pragma unroll
    for (int j = 0; j < 8; j++)
        out[j] = make_float4(di * h[j].x, di * h[j].y, di * h[j].z, di * h[j].w);

    g_cw[n] = di * (g_csum[n] + di);
}

// ---------------- kernel F: layer-2 aggregation + layer-3 + weighted reduce ----
__global__ void k_agg(const float* __restrict__ b2, const float* __restrict__ W3) {
    __shared__ double s_out[10];
    int t = threadIdx.x;
    int lane = t & 31;
    if (t < 10) s_out[t] = 0.0;
    __syncthreads();

    int n = blockIdx.x * (blockDim.x >> 5) + (t >> 5);

    // per-lane row of W3 [32,10] and b2 element
    float w3[10];
    #pragma unroll
    for (int j = 0; j < 10; j++) w3[j] = W3[lane * 10 + j];
    float b2l = b2[lane];

    if (n < N_NODES) {
        int cnt = g_cnt[n]; if (cnt > SLOTS) cnt = SLOTS;
        float du = g_dinv[n];
        const int* __restrict__ row = &g_slots[n * SLOTS];
        float acc = g_h2g[n * 32 + lane];     // self-loop term (× du at end)

        int e = 0;
        for (; e + 4 <= cnt; e += 4) {
            int s0 = row[e], s1 = row[e + 1], s2 = row[e + 2], s3 = row[e + 3];
            float v0 = g_h2g[s0 * 32 + lane];
            float v1 = g_h2g[s1 * 32 + lane];
            float v2 = g_h2g[s2 * 32 + lane];
            float v3 = g_h2g[s3 * 32 + lane];
            acc += (v0 + v1) + (v2 + v3);
        }
        for (; e < cnt; e++) acc += g_h2g[row[e] * 32 + lane];

        float v = fmaf(acc, du, b2l);         // agg2 + b2
        float a2 = v > 0.f ? v : 0.1f * v;    // leaky_relu(0.1)
        float cw = g_cw[n];

        #pragma unroll
        for (int j = 0; j < 10; j++) {
            float p = a2 * w3[j];
            #pragma unroll
            for (int o = 16; o; o >>= 1) p += __shfl_down_sync(0xffffffffu, p, o);
            if (lane == 0) atomicAdd(&s_out[j], (double)(cw * p));
        }
    }
    __syncthreads();
    if (t < 10) atomicAdd(&g_acc[t], s_out[t]);
}

// ---------------- kernel G: finalize ----------------
__global__ void k_final(const float* __restrict__ b3, float* __restrict__ out) {
    int j = threadIdx.x;
    if (j < 10) out[j] = (float)(g_acc[j] * (1.0 / (double)N_NODES)) + b3[j];
}

// ---------------- launch ----------------
extern "C" void kernel_launch(void* const* d_in, const int* in_sizes, int n_in,
                              void* d_out, int out_size) {
    const float* x   = (const float*)d_in[0];
    const int*   ei  = (const int*)  d_in[1];   // [2, E] row-major
    const float* W1  = (const float*)d_in[2];
    const float* b1  = (const float*)d_in[3];
    const float* W2  = (const float*)d_in[4];
    const float* b2  = (const float*)d_in[5];
    const float* W3  = (const float*)d_in[6];
    const float* b3  = (const float*)d_in[7];
    float* out = (float*)d_out;

    const int* src = ei;
    const int* dst = ei + N_EDGES;

    k_zero<<<(N_NODES + 255) / 256, 256>>>();
    k_scatter<<<(N_EDGES + 255) / 256, 256>>>(src, dst);
    k_node_init<<<(N_NODES + 255) / 256, 256>>>(x);
    k_s1_csum<<<(N_NODES * 32 + 255) / 256, 256>>>();
    k_mlp<<<(N_NODES + 255) / 256, 256>>>(W1, b1, W2);
    k_agg<<<(N_NODES * 32 + 255) / 256, 256>>>(b2, W3);
    k_final<<<1, 32>>>(b3, out);
}